// round 6
// baseline (speedup 1.0000x reference)
#include <cuda_runtime.h>

// y[i,o,n] = sum_j sum_k x[j,(o-1)%28, n+k-1]*W[i,j,0,k]
//                      + x[j,(o-2)%28, n+k-1]*W[i,j,1,k]
// x: (64,28,28) f32, W: (128,64,2,3) f32, y: (128,28,28) f32, zero-pad over n.
//
// Stage 1: grid (4,14,16) = 896 blocks x 256 thr (~48 warps/SM).
//   Block: 32 channels x 2 o-rows x 28 n, 4 j-channels. Thread tile 4i x 2n.
//   Partials -> __device__ scratch via STG.64 (no atomics).
// Stage 2: 196 blocks x 256 thr; 2 threads per float4 output (8 partials each),
//   combined via smem.

#define JT 4    // j per block (stage 1)
#define IC 32   // channels per block
#define NSPLIT 16

__device__ __align__(16) float g_scratch[NSPLIT * 128 * 28 * 28];

__global__ __launch_bounds__(256, 6)
void conv_partial_kernel(const float* __restrict__ x,
                         const float* __restrict__ W) {
    // 4 x-rows staged padded: padded index p = n+1, p=0..29 (stride 34 de-phases banks)
    __shared__ __align__(16) float xs[JT][4][34];
    // weights: [j][i_local][ l*4 + k ], float4-loadable; slots 3,7 are pad
    __shared__ __align__(16) float ws[JT][IC][8];

    const int tid = threadIdx.x;
    const int ib = blockIdx.x * IC;  // channel base
    const int ob = blockIdx.y * 2;   // o base (0..26, step 2)
    const int jb = blockIdx.z * JT;  // j base

    // Zero the n-pad columns
    if (tid < JT * 4) {
        int jl = tid >> 2, rl = tid & 3;
        xs[jl][rl][0]  = 0.0f;
        xs[jl][rl][29] = 0.0f;
    }
    // Stage x rows: row_local rl = global row (ob - 2 + rl) mod 28, rl = 0..3
    for (int idx = tid; idx < JT * 4 * 28; idx += 256) {
        int jl  = idx / 112;
        int rem = idx - jl * 112;
        int rl  = rem / 28;
        int n   = rem - rl * 28;
        int row = ob - 2 + rl;
        if (row < 0) row += 28;
        if (row >= 28) row -= 28;
        xs[jl][rl][n + 1] = x[(jb + jl) * 784 + row * 28 + n];
    }
    // Stage weights
    for (int idx = tid; idx < JT * IC * 6; idx += 256) {
        int jl  = idx / (IC * 6);
        int rem = idx - jl * (IC * 6);
        int il  = rem / 6;
        int q   = rem - il * 6;
        int l   = q / 3;
        int k   = q - l * 3;
        ws[jl][il][l * 4 + k] = W[(ib + il) * 384 + (jb + jl) * 6 + l * 3 + k];
    }
    __syncthreads();

    const int warp = tid >> 5;
    const int lane = tid & 31;
    const int ol = lane / 14;  // 0,1 (lanes 28..31 -> 2, redundant, masked at store)
    const int ng = lane % 14;  // 0..13 -> n0 = 2*ng
    const int il0 = warp * 4;
    const int n0 = 2 * ng;

    float acc[4][2];
    #pragma unroll
    for (int c = 0; c < 4; c++) { acc[c][0] = 0.0f; acc[c][1] = 0.0f; }

    #pragma unroll
    for (int jl = 0; jl < JT; jl++) {
        // taps: output cols n0,n0+1 need padded indices n0 .. n0+3
        const float* p1 = &xs[jl][ol + 1][n0]; // row (o-1) -> l=0 weights
        const float* p2 = &xs[jl][ol][n0];     // row (o-2) -> l=1 weights

        float v1[4], v2[4];
        {
            float2 u;
            u = *reinterpret_cast<const float2*>(p1);     v1[0] = u.x; v1[1] = u.y;
            u = *reinterpret_cast<const float2*>(p1 + 2); v1[2] = u.x; v1[3] = u.y;
            u = *reinterpret_cast<const float2*>(p2);     v2[0] = u.x; v2[1] = u.y;
            u = *reinterpret_cast<const float2*>(p2 + 2); v2[2] = u.x; v2[3] = u.y;
        }

        #pragma unroll
        for (int c = 0; c < 4; c++) {
            const float4 a0 = *reinterpret_cast<const float4*>(&ws[jl][il0 + c][0]); // l=0
            const float4 a1 = *reinterpret_cast<const float4*>(&ws[jl][il0 + c][4]); // l=1
            #pragma unroll
            for (int n = 0; n < 2; n++) {
                acc[c][n] = fmaf(v1[n + 0], a0.x, acc[c][n]);
                acc[c][n] = fmaf(v1[n + 1], a0.y, acc[c][n]);
                acc[c][n] = fmaf(v1[n + 2], a0.z, acc[c][n]);
                acc[c][n] = fmaf(v2[n + 0], a1.x, acc[c][n]);
                acc[c][n] = fmaf(v2[n + 1], a1.y, acc[c][n]);
                acc[c][n] = fmaf(v2[n + 2], a1.z, acc[c][n]);
            }
        }
    }

    if (lane < 28) {
        const int o = ob + ol;
        float* base = g_scratch + blockIdx.z * (128 * 784) + o * 28 + n0;
        #pragma unroll
        for (int c = 0; c < 4; c++) {
            float2 v = make_float2(acc[c][0], acc[c][1]);
            *reinterpret_cast<float2*>(base + (ib + il0 + c) * 784) = v;
        }
    }
}

__global__ __launch_bounds__(256, 8)
void reduce_kernel(float* __restrict__ out) {
    // 25088 float4 outputs; 196 blocks x 256 threads; 2 threads per output,
    // each sums 8 of the 16 partials, combined through smem.
    __shared__ float4 buf[128];
    const int t  = threadIdx.x;
    const int h  = t >> 7;                       // 0 or 1: which partial half
    const int o4 = blockIdx.x * 128 + (t & 127); // 0..25087
    const float4* s = reinterpret_cast<const float4*>(g_scratch);

    float4 r = make_float4(0.f, 0.f, 0.f, 0.f);
    #pragma unroll
    for (int p = 0; p < 8; p++) {
        float4 v = s[(8 * h + p) * 25088 + o4];
        r.x += v.x; r.y += v.y; r.z += v.z; r.w += v.w;
    }
    if (h) buf[t & 127] = r;
    __syncthreads();
    if (!h) {
        float4 b = buf[t];
        r.x += b.x; r.y += b.y; r.z += b.z; r.w += b.w;
        reinterpret_cast<float4*>(out)[o4] = r;
    }
}

extern "C" void kernel_launch(void* const* d_in, const int* in_sizes, int n_in,
                              void* d_out, int out_size) {
    const float* x = (const float*)d_in[0];  // (1,64,28,28)  = 50176 f32
    const float* W = (const float*)d_in[1];  // (128,64,2,3) = 147456 f32
    float* out = (float*)d_out;              // (1,128,28,28) = 100352 f32

    dim3 grid(4, 14, NSPLIT);  // (i-groups of 32, o-groups of 2, j-groups of 4)
    conv_partial_kernel<<<grid, 256>>>(x, W);
    reduce_kernel<<<196, 256>>>(out);
}

// round 7
// speedup vs baseline: 1.1575x; 1.1575x over previous
#include <cuda_runtime.h>

// y[i,o,n] = sum_j sum_k x[j,(o-1)%28, n+k-1]*W[i,j,0,k]
//                      + x[j,(o-2)%28, n+k-1]*W[i,j,1,k]
// x: (64,28,28) f32, W: (128,64,2,3) f32, y: (128,28,28) f32, zero-pad over n.
//
// Stage 1: grid (8,7,8) = 448 blocks x 128 thr. Block: 16 ch x 4 o x 28 n, 8 j.
//   Inner math in packed fma.rn.f32x2 (FFMA2): thread tile 4i x 4n as 2 f32x2
//   accumulator pairs per channel. Weights stored duplicated (w,w) in smem and
//   loaded as u64 pairs; x taps loaded as aligned b64 pairs.
//   Partials -> __device__ scratch via STG.128 (no atomics).
// Stage 2: 98 blocks x 256 thr; each thread sums 8 float4 partials -> out.

#define JT 8    // j per block (stage 1)
#define IC 16   // channels per block
#define NSPLIT 8

typedef unsigned long long u64;

__device__ __align__(16) float g_scratch[NSPLIT * 128 * 28 * 28];

static __device__ __forceinline__ u64 pk2(float a, float b) {
    u64 r; asm("mov.b64 %0, {%1, %2};" : "=l"(r) : "f"(a), "f"(b)); return r;
}
static __device__ __forceinline__ void up2(float& a, float& b, u64 v) {
    asm("mov.b64 {%0, %1}, %2;" : "=f"(a), "=f"(b) : "l"(v));
}
static __device__ __forceinline__ void fma2(u64& d, u64 a, u64 b) {
    asm("fma.rn.f32x2 %0, %1, %2, %0;" : "+l"(d) : "l"(a), "l"(b));
}
static __device__ __forceinline__ u64 lds64(unsigned sa) {
    u64 r; asm("ld.shared.b64 %0, [%1];" : "=l"(r) : "r"(sa)); return r;
}
static __device__ __forceinline__ void lds128_2x64(u64& a, u64& b, unsigned sa) {
    asm("ld.shared.v2.b64 {%0, %1}, [%2];" : "=l"(a), "=l"(b) : "r"(sa));
}

__global__ __launch_bounds__(128, 4)
void conv_partial_kernel(const float* __restrict__ x,
                         const float* __restrict__ W) {
    // x rows staged padded: padded index p = n+1, p=0..29 (stride 34 de-phases banks)
    __shared__ __align__(16) float xs[JT][6][34];
    // weights duplicated: ws2[jl][il][2*m .. 2*m+1] = (w, w), m = l*3+k (12 floats/row)
    __shared__ __align__(16) float ws2[JT][IC][12];

    const int tid = threadIdx.x;
    const int ib = blockIdx.x * IC;  // channel base
    const int ob = blockIdx.y * 4;   // o base (0..24)
    const int jb = blockIdx.z * JT;  // j base

    // Zero the n-pad columns
    if (tid < JT * 6) {
        int jl = tid / 6, rl = tid - jl * 6;
        xs[jl][rl][0]  = 0.0f;
        xs[jl][rl][29] = 0.0f;
    }
    // Stage x rows: row_local rl = global row (ob - 2 + rl) mod 28
    for (int idx = tid; idx < JT * 6 * 28; idx += 128) {
        int jl  = idx / 168;
        int rem = idx - jl * 168;
        int rl  = rem / 28;
        int n   = rem - rl * 28;
        int row = ob - 2 + rl;
        if (row < 0) row += 28;
        if (row >= 28) row -= 28;
        xs[jl][rl][n + 1] = x[(jb + jl) * 784 + row * 28 + n];
    }
    // Stage duplicated weights
    for (int idx = tid; idx < JT * IC * 6; idx += 128) {
        int jl  = idx / (IC * 6);
        int rem = idx - jl * (IC * 6);
        int il  = rem / 6;
        int m   = rem - il * 6;      // m = l*3 + k
        int l   = m / 3;
        int k   = m - l * 3;
        float w = W[(ib + il) * 384 + (jb + jl) * 6 + l * 3 + k];
        ws2[jl][il][2 * m]     = w;
        ws2[jl][il][2 * m + 1] = w;
    }
    __syncthreads();

    const int warp = tid >> 5;
    const int lane = tid & 31;
    const int ol = lane / 7;   // 0..3 (lanes 28..31 compute redundantly, masked at store)
    const int ng = lane % 7;   // 0..6 -> n0 = 4*ng
    const int il0 = warp * 4;
    const int n0 = 4 * ng;

    u64 acc[4][2];
    #pragma unroll
    for (int c = 0; c < 4; c++) { acc[c][0] = 0ULL; acc[c][1] = 0ULL; }

    // shared-space base addresses
    const unsigned xs_sa = (unsigned)__cvta_generic_to_shared(&xs[0][0][0]);
    const unsigned ws_sa = (unsigned)__cvta_generic_to_shared(&ws2[0][0][0]);

    #pragma unroll
    for (int jl = 0; jl < JT; jl++) {
        // Row (o-1) = xs[jl][ol+1], row (o-2) = xs[jl][ol]; taps n0..n0+5 (padded idx)
        const unsigned r1 = xs_sa + (unsigned)((jl * 6 + ol + 1) * 34 + n0) * 4u;
        const unsigned r2 = xs_sa + (unsigned)((jl * 6 + ol) * 34 + n0) * 4u;

        u64 Q0 = lds64(r1), Q2 = lds64(r1 + 8), Q4 = lds64(r1 + 16);
        u64 R0 = lds64(r2), R2 = lds64(r2 + 8), R4 = lds64(r2 + 16);

        float q0, q1, q2, q3, q4, q5;
        up2(q0, q1, Q0); up2(q2, q3, Q2); up2(q4, q5, Q4);
        u64 Q1 = pk2(q1, q2), Q3 = pk2(q3, q4);
        float s0, s1, s2, s3, s4, s5;
        up2(s0, s1, R0); up2(s2, s3, R2); up2(s4, s5, R4);
        u64 R1 = pk2(s1, s2), R3 = pk2(s3, s4);

        #pragma unroll
        for (int c = 0; c < 4; c++) {
            const unsigned wsa = ws_sa + (unsigned)((jl * IC + il0 + c) * 12) * 4u;
            u64 w01, w23, w45, w67_lo, wpad;
            // 6 duplicated pairs = 48B: m-order (l0k0,l0k1,l0k2,l1k0,l1k1,l1k2)
            lds128_2x64(w01, w23, wsa);        // pairs m0, m1
            lds128_2x64(w45, w67_lo, wsa + 16);// pairs m2, m3
            u64 w89, wAB;
            lds128_2x64(w89, wAB, wsa + 32);   // pairs m4, m5
            (void)wpad;

            // acc pair 0 (cols n0+0, n0+1)
            fma2(acc[c][0], Q0, w01);   // l=0,k=0
            fma2(acc[c][0], Q1, w23);   // l=0,k=1
            fma2(acc[c][0], Q2, w45);   // l=0,k=2
            fma2(acc[c][0], R0, w67_lo);// l=1,k=0
            fma2(acc[c][0], R1, w89);   // l=1,k=1
            fma2(acc[c][0], R2, wAB);   // l=1,k=2
            // acc pair 1 (cols n0+2, n0+3)
            fma2(acc[c][1], Q2, w01);
            fma2(acc[c][1], Q3, w23);
            fma2(acc[c][1], Q4, w45);
            fma2(acc[c][1], R2, w67_lo);
            fma2(acc[c][1], R3, w89);
            fma2(acc[c][1], R4, wAB);
        }
    }

    if (lane < 28) {
        const int o = ob + ol;
        float* base = g_scratch + blockIdx.z * (128 * 784) + o * 28 + n0;
        #pragma unroll
        for (int c = 0; c < 4; c++) {
            float4 v;
            up2(v.x, v.y, acc[c][0]);
            up2(v.z, v.w, acc[c][1]);
            *reinterpret_cast<float4*>(base + (ib + il0 + c) * 784) = v;
        }
    }
}

__global__ __launch_bounds__(256, 8)
void reduce_kernel(float* __restrict__ out) {
    // 25088 float4 outputs; 98 blocks x 256 threads; each thread sums NSPLIT partials.
    const int o4 = blockIdx.x * 256 + threadIdx.x;  // 0..25087
    const float4* s = reinterpret_cast<const float4*>(g_scratch);

    float4 r = make_float4(0.f, 0.f, 0.f, 0.f);
    #pragma unroll
    for (int p = 0; p < NSPLIT; p++) {
        float4 v = s[p * 25088 + o4];
        r.x += v.x; r.y += v.y; r.z += v.z; r.w += v.w;
    }
    reinterpret_cast<float4*>(out)[o4] = r;
}

extern "C" void kernel_launch(void* const* d_in, const int* in_sizes, int n_in,
                              void* d_out, int out_size) {
    const float* x = (const float*)d_in[0];  // (1,64,28,28)  = 50176 f32
    const float* W = (const float*)d_in[1];  // (128,64,2,3) = 147456 f32
    float* out = (float*)d_out;              // (1,128,28,28) = 100352 f32

    dim3 grid(8, 7, NSPLIT);  // (i-groups of 16, o-groups of 4, j-groups of 8)
    conv_partial_kernel<<<grid, 128>>>(x, W);
    reduce_kernel<<<98, 256>>>(out);
}